// round 15
// baseline (speedup 1.0000x reference)
#include <cuda_runtime.h>
#include <cuda_bf16.h>
#include <cstdint>

// ============================================================================
// Problem constants
// ============================================================================
#define BATCH   65536
#define KDIM    3072
#define HDIM    1024
#define NEXP    3

// GEMM tiling: 128x128 CTA tile, 4 warps of 64x64, 3-stage mbarrier pipeline,
// 2 CTAs/SM
#define BM      128
#define BN      128
#define BK      32
#define STAGES  3
#define NTHREADS 128
#define LDSF    36                      // smem row stride in floats (144 B: 16B-aligned, conflict-free)
#define A_STAGE (BM * LDSF)             // 4608 floats
#define B_STAGE (BN * LDSF)             // 4608 floats
#define SMEM_FLOATS (STAGES * (A_STAGE + B_STAGE))
#define SMEM_BYTES  (SMEM_FLOATS * 4 + 64)  // +64 for 6 mbarriers; 110656 -> 2 CTAs/SM

#define NKITER  (KDIM / BK)             // 96

// ============================================================================
// Device scratch (no cudaMalloc allowed)
// ============================================================================
__device__ float g_w1t[HDIM * KDIM];    // w1 transposed to [n][k], tf32-rna rounded
__device__ float g_logits[BATCH * NEXP];
__device__ float g_rlogits[BATCH * NEXP];
__device__ int   g_ridx[BATCH];
__device__ int   g_rcount;

#define RMAX 4096
__device__ float g_hpart[RMAX * HDIM];  // k-split partial h staging for refinement

// ============================================================================
// Helpers
// ============================================================================
__device__ __forceinline__ uint32_t smem_u32(const void* p) {
    uint32_t a;
    asm("{ .reg .u64 t; cvta.to.shared.u64 t, %1; cvt.u32.u64 %0, t; }" : "=r"(a) : "l"(p));
    return a;
}

// cvt.rna.tf32.f32 requires a .b32 destination register
__device__ __forceinline__ float to_tf32_rna(float f) {
    uint32_t r;
    asm("cvt.rna.tf32.f32 %0, %1;" : "=r"(r) : "f"(f));
    return __uint_as_float(r);
}

#define CP_ASYNC_16(saddr, gaddr) \
    asm volatile("cp.async.cg.shared.global [%0], [%1], 16;" :: "r"(saddr), "l"(gaddr))

// mbarrier primitives (sm_80+, legal at compute_100)
#define MBARRIER_INIT(mbar, cnt) \
    asm volatile("mbarrier.init.shared.b64 [%0], %1;" :: "r"((uint32_t)(mbar)), "r"((uint32_t)(cnt)) : "memory")
#define MBARRIER_ARRIVE(mbar) \
    asm volatile("mbarrier.arrive.shared.b64 _, [%0];" :: "r"((uint32_t)(mbar)) : "memory")
// one arrival per thread when all of this thread's prior cp.async complete
#define CP_MBAR_ARRIVE(mbar) \
    asm volatile("cp.async.mbarrier.arrive.noinc.shared.b64 [%0];" :: "r"((uint32_t)(mbar)) : "memory")

#define MBARRIER_WAIT(mbar, parity) do {                                                     \
    uint32_t _m = (uint32_t)(mbar);                                                          \
    uint32_t _p = (uint32_t)(parity);                                                        \
    uint32_t _done;                                                                          \
    asm volatile("{\n\t.reg .pred p;\n\t"                                                    \
                 "mbarrier.try_wait.parity.shared.b64 p, [%1], %2;\n\t"                      \
                 "selp.b32 %0, 1, 0, p;\n\t}"                                                \
                 : "=r"(_done) : "r"(_m), "r"(_p) : "memory");                               \
    if (!_done) {                                                                            \
        asm volatile("{\n\t.reg .pred P1;\n\t"                                               \
            "WL_%=:\n\t"                                                                     \
            "mbarrier.try_wait.parity.shared.b64 P1, [%0], %1;\n\t"                          \
            "@P1 bra.uni WD_%=;\n\t"                                                         \
            "bra.uni WL_%=;\n\t"                                                             \
            "WD_%=:\n\t}" :: "r"(_m), "r"(_p) : "memory");                                   \
    }                                                                                        \
} while (0)

__device__ __forceinline__ void mma_tf32(float* d, const uint32_t* a, const uint32_t* b) {
    asm volatile(
        "mma.sync.aligned.m16n8k8.row.col.f32.tf32.tf32.f32 "
        "{%0,%1,%2,%3}, {%4,%5,%6,%7}, {%8,%9}, {%0,%1,%2,%3};"
        : "+f"(d[0]), "+f"(d[1]), "+f"(d[2]), "+f"(d[3])
        : "r"(a[0]), "r"(a[1]), "r"(a[2]), "r"(a[3]), "r"(b[0]), "r"(b[1]));
}

__device__ __forceinline__ float gelu_exact(float x) {
    return 0.5f * x * (1.0f + erff(x * 0.70710678118654752f));
}

__device__ __forceinline__ int read_k(const int* kp) {
    int v = *kp;
    if (v > 100000 || v < -100000) {      // hedge: k delivered as fp32 bits
        float f = __int_as_float(v);
        v = (int)f;
    }
    if (v > NEXP) v = NEXP;
    return v;
}

// softmax + top-k mask + renormalized gates (jax top_k: ties prefer lower index)
__device__ __forceinline__ void gate_from_logits(float l0, float l1, float l2, int k,
                                                 float* gated, float* mask) {
    float mx = fmaxf(l0, fmaxf(l1, l2));
    float e0 = expf(l0 - mx), e1 = expf(l1 - mx), e2 = expf(l2 - mx);
    float s = e0 + e1 + e2;
    float g[3] = {e0 / s, e1 / s, e2 / s};
    float m[3] = {0.f, 0.f, 0.f};
    if (k >= 3) {
        m[0] = m[1] = m[2] = 1.f;
    } else if (k == 2) {
        int lo = 0;                        // excluded = min; ties -> largest index excluded
        if (g[1] <= g[lo]) lo = 1;
        if (g[2] <= g[lo]) lo = 2;
        m[0] = m[1] = m[2] = 1.f;
        m[lo] = 0.f;
    } else if (k == 1) {
        int w = 0;                         // winner = max; ties -> lowest index
        if (g[1] > g[w]) w = 1;
        if (g[2] > g[w]) w = 2;
        m[w] = 1.f;
    }
    float ssum = g[0] * m[0] + g[1] * m[1] + g[2] * m[2] + 1e-8f;
    gated[0] = g[0] * m[0] / ssum;
    gated[1] = g[1] * m[1] / ssum;
    gated[2] = g[2] * m[2] / ssum;
    mask[0] = m[0]; mask[1] = m[1]; mask[2] = m[2];
}

// ============================================================================
// Kernel 0: smem-tiled transpose w1 -> [n][k] + tf32 rounding   (launch idx 0)
// ============================================================================
__global__ void prep_transpose(const float* __restrict__ w1) {
    __shared__ float t[32][33];
    int bn = blockIdx.x & 31;            // n tile (HDIM/32 = 32)
    int bk = blockIdx.x >> 5;            // k tile (KDIM/32 = 96)
    int tx = threadIdx.x & 31;
    int ty = threadIdx.x >> 5;           // 0..7

    #pragma unroll
    for (int i = 0; i < 4; ++i)          // read w1[kk][n], coalesced over n
        t[ty + i * 8][tx] = w1[(size_t)(bk * 32 + ty + i * 8) * HDIM + bn * 32 + tx];
    __syncthreads();
    #pragma unroll
    for (int i = 0; i < 4; ++i)          // write g_w1t[n][kk], coalesced over kk
        g_w1t[(size_t)(bn * 32 + ty + i * 8) * KDIM + bk * 32 + tx] =
            to_tf32_rna(t[tx][ty + i * 8]);
}

// Kernel 0b: zero logits accumulator                             (launch idx 1)
__global__ void prep_zero() {
    int stride = gridDim.x * blockDim.x;
    for (int i = blockIdx.x * blockDim.x + threadIdx.x; i < BATCH * NEXP; i += stride)
        g_logits[i] = 0.f;
}

// Kernel 0c: reset refinement counter                            (launch idx 2)
__global__ void prep_init() {
    if (threadIdx.x == 0 && blockIdx.x == 0) g_rcount = 0;
}

// ============================================================================
// Kernel 1 (launch idx 3 -> ncu capture slot): tf32 mma.sync GEMM (h = x @ w1)
// fused with +b1, GELU, and h@w2 as per-row 3-float partial dots -> atomicAdd.
//   CTA tile 128x128, 4 warps (2x2) of 64x64, 128 threads, 2 CTAs/SM.
//   mbarrier producer/consumer ring; full-wait for stage kt+1 is hoisted into
//   ks=3 of kt with cross-stage fragment prefetch into the idle register
//   buffer — removes the post-wait LDS bubble that ptxas cannot hoist across
//   a barrier. Empty-barrier arrivals are warp-elected (count 4).
// ============================================================================
__global__ void __launch_bounds__(NTHREADS, 2)
gemm_kernel(const float* __restrict__ x, const float* __restrict__ b1,
            const float* __restrict__ w2) {
    extern __shared__ float smem[];
    float* As = smem;                        // [STAGES][BM][LDSF]
    float* Bs = smem + STAGES * A_STAGE;     // [STAGES][BN][LDSF]

    const int tid  = threadIdx.x;
    const int wid  = tid >> 5;
    const int lane = tid & 31;

    const int mt = blockIdx.x >> 3;
    const int nt = blockIdx.x & 7;
    const int m0 = mt * BM;
    const int n0 = nt * BN;

    const int wm = (wid >> 1) * 64;          // warp row offset (0/64)
    const int wn = (wid & 1) * 64;           // warp col offset (0/64)

    const uint32_t a_base = smem_u32(As);
    const uint32_t b_base = smem_u32(Bs);
    const uint32_t mb     = smem_u32(smem) + (uint32_t)SMEM_FLOATS * 4u;
    // full[s] = mb + s*8 ; empty[s] = mb + 24 + s*8

    if (tid == 0) {
        #pragma unroll
        for (int s = 0; s < STAGES; ++s) {
            MBARRIER_INIT(mb + s * 8, NTHREADS);      // full: 128 cp-arrivals
            MBARRIER_INIT(mb + 24 + s * 8, 4);        // empty: warp-elected
        }
    }
    __syncthreads();

    // ---- async copy of one stage (A: x fp32 raw; B: pre-rounded w1t) -------
    auto copy_stage = [&](int s, int k0) {
        const float* xg = x + (size_t)m0 * KDIM + k0;
        const float* bg = g_w1t + (size_t)n0 * KDIM + k0;
        uint32_t sa = a_base + (uint32_t)(s * A_STAGE) * 4u;
        uint32_t sb = b_base + (uint32_t)(s * B_STAGE) * 4u;
        #pragma unroll
        for (int i = 0; i < 8; ++i) {        // A: 1024 16B-chunks
            int f  = tid + i * NTHREADS;
            int m  = f >> 3;
            int kc = f & 7;
            CP_ASYNC_16(sa + (uint32_t)(m * LDSF + kc * 4) * 4u,
                        (const void*)(xg + (size_t)m * KDIM + kc * 4));
        }
        #pragma unroll
        for (int i = 0; i < 8; ++i) {        // B: 1024 16B-chunks
            int f  = tid + i * NTHREADS;
            int m  = f >> 3;
            int kc = f & 7;
            CP_ASYNC_16(sb + (uint32_t)(m * LDSF + kc * 4) * 4u,
                        (const void*)(bg + (size_t)m * KDIM + kc * 4));
        }
    };

    int pst = 0, pph = 1;        // producer cursor (phase 1: first empty-wait passes)

    auto fill = [&](int k0) {
        MBARRIER_WAIT(mb + 24 + pst * 8, (uint32_t)pph);   // wait stage empty
        copy_stage(pst, k0);
        CP_MBAR_ARRIVE(mb + pst * 8);                      // arrive full on completion
        if (++pst == STAGES) { pst = 0; pph ^= 1; }
    };

    const int r  = lane >> 2;     // 0..7
    const int c4 = lane & 3;      // 0..3

    // fragment loader: one ks step of the stage at (Asr, Bsr)
    auto load_frags = [&](const float* Asr, const float* Bsr, int ks,
                          uint32_t* afb, uint32_t* bfb) {
        #pragma unroll
        for (int fm = 0; fm < 4; ++fm) {
            const float* ap = Asr + fm * 16 * LDSF + ks * 8 + c4;
            afb[fm * 4 + 0] = __float_as_uint(ap[0]);
            afb[fm * 4 + 1] = __float_as_uint(ap[8 * LDSF]);
            afb[fm * 4 + 2] = __float_as_uint(ap[4]);
            afb[fm * 4 + 3] = __float_as_uint(ap[8 * LDSF + 4]);
        }
        #pragma unroll
        for (int fn = 0; fn < 8; ++fn) {
            const float* bp = Bsr + fn * 8 * LDSF + ks * 8 + c4;
            bfb[fn * 2 + 0] = __float_as_uint(bp[0]);
            bfb[fn * 2 + 1] = __float_as_uint(bp[4]);
        }
    };

    // ---- prologue -----------------------------------------------------------
    fill(0);
    fill(BK);

    float acc[4][8][4];
    #pragma unroll
    for (int a = 0; a < 4; ++a)
        #pragma unroll
        for (int b = 0; b < 8; ++b)
            #pragma unroll
            for (int c = 0; c < 4; ++c) acc[a][b][c] = 0.f;

    MBARRIER_WAIT(mb + 0, 0u);             // full[0], phase 0
    int wst = 0, wph = 0;                  // full-wait cursor (already past stage 0)
    int cst = 0, cph = 0;                  // consumer arrive cursor

    uint32_t af[2][16];
    uint32_t bf[2][16];
    load_frags(As + (wm + r) * LDSF, Bs + (wn + r) * LDSF, 0, af[0], bf[0]);

    // ---- main loop ----------------------------------------------------------
    for (int kt = 0; kt < NKITER; ++kt) {
        int nk = kt + STAGES - 1;
        if (nk < NKITER) fill(nk * BK);

        const float* AsrC = As + cst * A_STAGE + (wm + r) * LDSF;
        const float* BsrC = Bs + cst * B_STAGE + (wn + r) * LDSF;

        #pragma unroll
        for (int ks = 0; ks < 4; ++ks) {
            const int cur = ks & 1;        // buf parity: 4 flips/kt -> 0 at kt start
            const int nxt = cur ^ 1;
            if (ks < 3) {
                load_frags(AsrC, BsrC, ks + 1, af[nxt], bf[nxt]);
            } else if (kt + 1 < NKITER) {
                // hoisted wait for next stage + cross-stage ks=0 prefetch
                if (++wst == STAGES) { wst = 0; wph ^= 1; }
                MBARRIER_WAIT(mb + wst * 8, (uint32_t)wph);
                const float* AsrN = As + wst * A_STAGE + (wm + r) * LDSF;
                const float* BsrN = Bs + wst * B_STAGE + (wn + r) * LDSF;
                load_frags(AsrN, BsrN, 0, af[nxt], bf[nxt]);
            }
            #pragma unroll
            for (int fm = 0; fm < 4; ++fm)
                #pragma unroll
                for (int fn = 0; fn < 8; ++fn)
                    mma_tf32(acc[fm][fn], &af[cur][fm * 4], &bf[cur][fn * 2]);
        }

        __syncwarp();
        if (lane == 0) MBARRIER_ARRIVE(mb + 24 + cst * 8);   // warp-elected
        if (++cst == STAGES) { cst = 0; cph ^= 1; }
    }

    // ---- fused epilogue: +b1, GELU, dot with w2, reduce, atomicAdd ----------
    float bias[16], w2c[16][3];
    #pragma unroll
    for (int fn = 0; fn < 8; ++fn)
        #pragma unroll
        for (int j = 0; j < 2; ++j) {
            int q = fn * 2 + j;
            int n = n0 + wn + fn * 8 + c4 * 2 + j;
            bias[q]   = __ldg(&b1[n]);
            w2c[q][0] = __ldg(&w2[n * 3 + 0]);
            w2c[q][1] = __ldg(&w2[n * 3 + 1]);
            w2c[q][2] = __ldg(&w2[n * 3 + 2]);
        }

    #pragma unroll
    for (int fm = 0; fm < 4; ++fm) {
        #pragma unroll
        for (int h = 0; h < 2; ++h) {
            int m = m0 + wm + fm * 16 + r + h * 8;
            float p0 = 0.f, p1 = 0.f, p2 = 0.f;
            #pragma unroll
            for (int fn = 0; fn < 8; ++fn)
                #pragma unroll
                for (int j = 0; j < 2; ++j) {
                    int q = fn * 2 + j;
                    float g = gelu_exact(acc[fm][fn][h * 2 + j] + bias[q]);
                    p0 = fmaf(g, w2c[q][0], p0);
                    p1 = fmaf(g, w2c[q][1], p1);
                    p2 = fmaf(g, w2c[q][2], p2);
                }
            p0 += __shfl_xor_sync(0xffffffffu, p0, 1);
            p0 += __shfl_xor_sync(0xffffffffu, p0, 2);
            p1 += __shfl_xor_sync(0xffffffffu, p1, 1);
            p1 += __shfl_xor_sync(0xffffffffu, p1, 2);
            p2 += __shfl_xor_sync(0xffffffffu, p2, 1);
            p2 += __shfl_xor_sync(0xffffffffu, p2, 2);
            if (c4 == 0) {
                atomicAdd(&g_logits[m * 3 + 0], p0);
                atomicAdd(&g_logits[m * 3 + 1], p1);
                atomicAdd(&g_logits[m * 3 + 2], p2);
            }
        }
    }
}

// ============================================================================
// Kernel 2: softmax / top-k / mask / gated + near-tie flagging
// ============================================================================
__global__ void finalize_kernel(const float* __restrict__ b2, const int* __restrict__ kptr,
                                float* __restrict__ out) {
    int row = blockIdx.x * blockDim.x + threadIdx.x;
    if (row >= BATCH) return;
    int k = read_k(kptr);
    float l0 = g_logits[row * 3 + 0] + b2[0];
    float l1 = g_logits[row * 3 + 1] + b2[1];
    float l2 = g_logits[row * 3 + 2] + b2[2];
    float gated[3], mask[3];
    gate_from_logits(l0, l1, l2, k, gated, mask);
    out[(size_t)row * 3 + 0] = gated[0];
    out[(size_t)row * 3 + 1] = gated[1];
    out[(size_t)row * 3 + 2] = gated[2];
    out[(size_t)BATCH * 3 + row * 3 + 0] = mask[0];
    out[(size_t)BATCH * 3 + row * 3 + 1] = mask[1];
    out[(size_t)BATCH * 3 + row * 3 + 2] = mask[2];

    // flag rows whose top-k boundary gap is within ~8 sigma of tf32 error
    if (k == 1 || k == 2) {
        float a = l0, b = l1, cv = l2, t;
        if (a < b)  { t = a; a = b; b = t; }
        if (b < cv) { t = b; b = cv; cv = t; }
        if (a < b)  { t = a; a = b; b = t; }
        float gap = (k == 1) ? (a - b) : (b - cv);
        if (gap < 4e-3f) {
            int j = atomicAdd(&g_rcount, 1);
            if (j < RMAX) g_ridx[j] = row;
        }
    }
}

// zero the k-split staging used by refine1 (count rows only)
__global__ void refine0_kernel() {
    int count = g_rcount;
    if (count > RMAX) count = RMAX;
    size_t total = (size_t)count * HDIM;
    for (size_t i = blockIdx.x * blockDim.x + threadIdx.x; i < total;
         i += (size_t)gridDim.x * blockDim.x)
        g_hpart[i] = 0.f;
}

// ============================================================================
// Kernel 3: fp32-exact partial h for flagged rows.
//   item = (16 rows) x (64 h-cols) x (768-k quarter). 256 thr = 16 rows x
//   16 col-quads. No smem/barriers. Double-buffered float4 w1 batches.
// ============================================================================
#define RB_ROWS 16
#define RK      768
__global__ void __launch_bounds__(256)
refine1_kernel(const float* __restrict__ x, const float* __restrict__ w1) {
    int count = g_rcount;
    if (count > RMAX) count = RMAX;
    if (count == 0) return;
    int mchunks = (count + RB_ROWS - 1) / RB_ROWS;
    int nitems = mchunks * 16 * 4;               // x16 n-chunks, x4 k-quarters

    int tid  = threadIdx.x;
    int rloc = tid >> 4;          // 0..15 row within chunk
    int cg   = tid & 15;          // col-quad index

    for (int item = blockIdx.x; item < nitems; item += gridDim.x) {
        int kc = item & 3;
        int nc = (item >> 2) & 15;
        int mc = item >> 6;
        int n = nc * 64 + cg * 4;
        int j = mc * RB_ROWS + rloc;
        int jc = (j < count) ? j : (count - 1);
        const float* xr = x + (size_t)g_ridx[jc] * KDIM + kc * RK;
        const float* wp = w1 + (size_t)kc * RK * HDIM + n;

        float a0 = 0.f, a1 = 0.f, a2 = 0.f, a3 = 0.f;
        float4 wa0, wa1, wa2, wa3, wb0, wb1, wb2, wb3;
        wa0 = __ldg(reinterpret_cast<const float4*>(wp + 0 * HDIM));
        wa1 = __ldg(reinterpret_cast<const float4*>(wp + 1 * HDIM));
        wa2 = __ldg(reinterpret_cast<const float4*>(wp + 2 * HDIM));
        wa3 = __ldg(reinterpret_cast<const float4*>(wp + 3 * HDIM));
        for (int kk = 0; kk < RK; kk += 8) {
            wb0 = __ldg(reinterpret_cast<const float4*>(wp + (size_t)(kk + 4) * HDIM));
            wb1 = __ldg(reinterpret_cast<const float4*>(wp + (size_t)(kk + 5) * HDIM));
            wb2 = __ldg(reinterpret_cast<const float4*>(wp + (size_t)(kk + 6) * HDIM));
            wb3 = __ldg(reinterpret_cast<const float4*>(wp + (size_t)(kk + 7) * HDIM));
            float4 xv = __ldg(reinterpret_cast<const float4*>(xr + kk));
            a0 = fmaf(xv.x, wa0.x, a0); a1 = fmaf(xv.x, wa0.y, a1);
            a2 = fmaf(xv.x, wa0.z, a2); a3 = fmaf(xv.x, wa0.w, a3);
            a0 = fmaf(xv.y, wa1.x, a0); a1 = fmaf(xv.y, wa1.y, a1);
            a2 = fmaf(xv.y, wa1.z, a2); a3 = fmaf(xv.y, wa1.w, a3);
            a0 = fmaf(xv.z, wa2.x, a0); a1 = fmaf(xv.z, wa2.y, a1);
            a2 = fmaf(xv.z, wa2.z, a2); a3 = fmaf(xv.z, wa2.w, a3);
            a0 = fmaf(xv.w, wa3.x, a0); a1 = fmaf(xv.w, wa3.y, a1);
            a2 = fmaf(xv.w, wa3.z, a2); a3 = fmaf(xv.w, wa3.w, a3);
            if (kk + 8 < RK) {
                wa0 = __ldg(reinterpret_cast<const float4*>(wp + (size_t)(kk + 8)  * HDIM));
                wa1 = __ldg(reinterpret_cast<const float4*>(wp + (size_t)(kk + 9)  * HDIM));
                wa2 = __ldg(reinterpret_cast<const float4*>(wp + (size_t)(kk + 10) * HDIM));
                wa3 = __ldg(reinterpret_cast<const float4*>(wp + (size_t)(kk + 11) * HDIM));
            }
            float4 xw = __ldg(reinterpret_cast<const float4*>(xr + kk + 4));
            a0 = fmaf(xw.x, wb0.x, a0); a1 = fmaf(xw.x, wb0.y, a1);
            a2 = fmaf(xw.x, wb0.z, a2); a3 = fmaf(xw.x, wb0.w, a3);
            a0 = fmaf(xw.y, wb1.x, a0); a1 = fmaf(xw.y, wb1.y, a1);
            a2 = fmaf(xw.y, wb1.z, a2); a3 = fmaf(xw.y, wb1.w, a3);
            a0 = fmaf(xw.z, wb2.x, a0); a1 = fmaf(xw.z, wb2.y, a1);
            a2 = fmaf(xw.z, wb2.z, a2); a3 = fmaf(xw.z, wb2.w, a3);
            a0 = fmaf(xw.w, wb3.x, a0); a1 = fmaf(xw.w, wb3.y, a1);
            a2 = fmaf(xw.w, wb3.z, a2); a3 = fmaf(xw.w, wb3.w, a3);
        }

        if (j < count) {
            float* dst = g_hpart + ((size_t)j * HDIM + n);
            atomicAdd(&dst[0], a0);
            atomicAdd(&dst[1], a1);
            atomicAdd(&dst[2], a2);
            atomicAdd(&dst[3], a3);
        }
    }
}

// combine partial h -> GELU -> dot w2 -> refined logits
__global__ void refine1b_kernel(const float* __restrict__ b1, const float* __restrict__ w2) {
    int count = g_rcount;
    if (count > RMAX) count = RMAX;
    int warps = (gridDim.x * blockDim.x) >> 5;
    int gw = (blockIdx.x * blockDim.x + threadIdx.x) >> 5;
    int lane = threadIdx.x & 31;
    for (int j = gw; j < count; j += warps) {
        float p0 = 0.f, p1 = 0.f, p2 = 0.f;
        for (int nb = 0; nb < HDIM; nb += 32) {
            int n = nb + lane;
            float h = g_hpart[(size_t)j * HDIM + n] + __ldg(&b1[n]);
            float g = gelu_exact(h);
            p0 = fmaf(g, __ldg(&w2[n * 3 + 0]), p0);
            p1 = fmaf(g, __ldg(&w2[n * 3 + 1]), p1);
            p2 = fmaf(g, __ldg(&w2[n * 3 + 2]), p2);
        }
        #pragma unroll
        for (int off = 16; off > 0; off >>= 1) {
            p0 += __shfl_xor_sync(0xffffffffu, p0, off);
            p1 += __shfl_xor_sync(0xffffffffu, p1, off);
            p2 += __shfl_xor_sync(0xffffffffu, p2, off);
        }
        if (lane == 0) {
            g_rlogits[j * 3 + 0] = p0;
            g_rlogits[j * 3 + 1] = p1;
            g_rlogits[j * 3 + 2] = p2;
        }
    }
}

// ============================================================================
// Kernel 4: rewrite outputs for flagged rows from refined (exact) logits
// ============================================================================
__global__ void refine2_kernel(const float* __restrict__ b2, const int* __restrict__ kptr,
                               float* __restrict__ out) {
    int k = read_k(kptr);
    int count = g_rcount;
    if (count > RMAX) count = RMAX;
    for (int j = blockIdx.x * blockDim.x + threadIdx.x; j < count; j += gridDim.x * blockDim.x) {
        int row = g_ridx[j];
        float l0 = g_rlogits[j * 3 + 0] + b2[0];
        float l1 = g_rlogits[j * 3 + 1] + b2[1];
        float l2 = g_rlogits[j * 3 + 2] + b2[2];
        float gated[3], mask[3];
        gate_from_logits(l0, l1, l2, k, gated, mask);
        out[(size_t)row * 3 + 0] = gated[0];
        out[(size_t)row * 3 + 1] = gated[1];
        out[(size_t)row * 3 + 2] = gated[2];
        out[(size_t)BATCH * 3 + row * 3 + 0] = mask[0];
        out[(size_t)BATCH * 3 + row * 3 + 1] = mask[1];
        out[(size_t)BATCH * 3 + row * 3 + 2] = mask[2];
    }
}

// ============================================================================
// Launch — gemm deliberately placed at launch index 3 (ncu capture slot)
// ============================================================================
extern "C" void kernel_launch(void* const* d_in, const int* in_sizes, int n_in,
                              void* d_out, int out_size) {
    const float* x  = (const float*)d_in[0];
    const float* w1 = (const float*)d_in[1];
    const float* b1 = (const float*)d_in[2];
    const float* w2 = (const float*)d_in[3];
    const float* b2 = (const float*)d_in[4];
    const int*   kp = (const int*)d_in[5];
    float* out = (float*)d_out;
    (void)in_sizes; (void)n_in; (void)out_size;

    static bool attr_set = false;
    if (!attr_set) {
        cudaFuncSetAttribute(gemm_kernel, cudaFuncAttributeMaxDynamicSharedMemorySize, SMEM_BYTES);
        attr_set = true;
    }

    prep_transpose<<<(HDIM / 32) * (KDIM / 32), 256>>>(w1);          // idx 0
    prep_zero<<<256, 256>>>();                                       // idx 1
    prep_init<<<1, 32>>>();                                          // idx 2
    gemm_kernel<<<(BATCH / BM) * (HDIM / BN), NTHREADS, SMEM_BYTES>>>(x, b1, w2);  // idx 3
    finalize_kernel<<<BATCH / 256, 256>>>(b2, kp, out);              // idx 4
    refine0_kernel<<<256, 256>>>();                                  // idx 5
    refine1_kernel<<<1024, 256>>>(x, w1);                            // idx 6
    refine1b_kernel<<<128, 256>>>(b1, w2);                           // idx 7
    refine2_kernel<<<64, 256>>>(b2, kp, out);                        // idx 8
}

// round 16
// speedup vs baseline: 1.1417x; 1.1417x over previous
#include <cuda_runtime.h>
#include <cuda_bf16.h>
#include <cstdint>

// ============================================================================
// Problem constants
// ============================================================================
#define BATCH   65536
#define KDIM    3072
#define HDIM    1024
#define NEXP    3

// GEMM tiling: 128x128 CTA tile, 4 warps of 64x64, 3-stage mbarrier pipeline,
// 2 CTAs/SM
#define BM      128
#define BN      128
#define BK      32
#define STAGES  3
#define NTHREADS 128
#define LDSF    36                      // smem row stride in floats (144 B: 16B-aligned, conflict-free)
#define A_STAGE (BM * LDSF)             // 4608 floats
#define B_STAGE (BN * LDSF)             // 4608 floats
#define SMEM_FLOATS (STAGES * (A_STAGE + B_STAGE))
#define SMEM_BYTES  (SMEM_FLOATS * 4 + 64)  // +64 for 6 mbarriers; 110656 -> 2 CTAs/SM

#define NKITER  (KDIM / BK)             // 96

// ============================================================================
// Device scratch (no cudaMalloc allowed)
// ============================================================================
__device__ float g_w1t[HDIM * KDIM];    // w1 transposed to [n][k], tf32-rna rounded
__device__ float g_logits[BATCH * NEXP];
__device__ float g_rlogits[BATCH * NEXP];
__device__ int   g_ridx[BATCH];
__device__ int   g_rcount;

#define RMAX 4096
__device__ float g_hpart[RMAX * HDIM];  // k-split partial h staging for refinement

// ============================================================================
// Helpers
// ============================================================================
__device__ __forceinline__ uint32_t smem_u32(const void* p) {
    uint32_t a;
    asm("{ .reg .u64 t; cvta.to.shared.u64 t, %1; cvt.u32.u64 %0, t; }" : "=r"(a) : "l"(p));
    return a;
}

// cvt.rna.tf32.f32 requires a .b32 destination register
__device__ __forceinline__ float to_tf32_rna(float f) {
    uint32_t r;
    asm("cvt.rna.tf32.f32 %0, %1;" : "=r"(r) : "f"(f));
    return __uint_as_float(r);
}

#define CP_ASYNC_16(saddr, gaddr) \
    asm volatile("cp.async.cg.shared.global [%0], [%1], 16;" :: "r"(saddr), "l"(gaddr))

// mbarrier primitives (sm_80+, legal at compute_100)
#define MBARRIER_INIT(mbar, cnt) \
    asm volatile("mbarrier.init.shared.b64 [%0], %1;" :: "r"((uint32_t)(mbar)), "r"((uint32_t)(cnt)) : "memory")
#define MBARRIER_ARRIVE(mbar) \
    asm volatile("mbarrier.arrive.shared.b64 _, [%0];" :: "r"((uint32_t)(mbar)) : "memory")
// one arrival per thread when all of this thread's prior cp.async complete
#define CP_MBAR_ARRIVE(mbar) \
    asm volatile("cp.async.mbarrier.arrive.noinc.shared.b64 [%0];" :: "r"((uint32_t)(mbar)) : "memory")

#define MBARRIER_WAIT(mbar, parity) do {                                                     \
    uint32_t _m = (uint32_t)(mbar);                                                          \
    uint32_t _p = (uint32_t)(parity);                                                        \
    uint32_t _done;                                                                          \
    asm volatile("{\n\t.reg .pred p;\n\t"                                                    \
                 "mbarrier.try_wait.parity.shared.b64 p, [%1], %2;\n\t"                      \
                 "selp.b32 %0, 1, 0, p;\n\t}"                                                \
                 : "=r"(_done) : "r"(_m), "r"(_p) : "memory");                               \
    if (!_done) {                                                                            \
        asm volatile("{\n\t.reg .pred P1;\n\t"                                               \
            "WL_%=:\n\t"                                                                     \
            "mbarrier.try_wait.parity.shared.b64 P1, [%0], %1;\n\t"                          \
            "@P1 bra.uni WD_%=;\n\t"                                                         \
            "bra.uni WL_%=;\n\t"                                                             \
            "WD_%=:\n\t}" :: "r"(_m), "r"(_p) : "memory");                                   \
    }                                                                                        \
} while (0)

__device__ __forceinline__ void mma_tf32(float* d, const uint32_t* a, const uint32_t* b) {
    asm volatile(
        "mma.sync.aligned.m16n8k8.row.col.f32.tf32.tf32.f32 "
        "{%0,%1,%2,%3}, {%4,%5,%6,%7}, {%8,%9}, {%0,%1,%2,%3};"
        : "+f"(d[0]), "+f"(d[1]), "+f"(d[2]), "+f"(d[3])
        : "r"(a[0]), "r"(a[1]), "r"(a[2]), "r"(a[3]), "r"(b[0]), "r"(b[1]));
}

__device__ __forceinline__ float gelu_exact(float x) {
    return 0.5f * x * (1.0f + erff(x * 0.70710678118654752f));
}

__device__ __forceinline__ int read_k(const int* kp) {
    int v = *kp;
    if (v > 100000 || v < -100000) {      // hedge: k delivered as fp32 bits
        float f = __int_as_float(v);
        v = (int)f;
    }
    if (v > NEXP) v = NEXP;
    return v;
}

// softmax + top-k mask + renormalized gates (jax top_k: ties prefer lower index)
__device__ __forceinline__ void gate_from_logits(float l0, float l1, float l2, int k,
                                                 float* gated, float* mask) {
    float mx = fmaxf(l0, fmaxf(l1, l2));
    float e0 = expf(l0 - mx), e1 = expf(l1 - mx), e2 = expf(l2 - mx);
    float s = e0 + e1 + e2;
    float g[3] = {e0 / s, e1 / s, e2 / s};
    float m[3] = {0.f, 0.f, 0.f};
    if (k >= 3) {
        m[0] = m[1] = m[2] = 1.f;
    } else if (k == 2) {
        int lo = 0;                        // excluded = min; ties -> largest index excluded
        if (g[1] <= g[lo]) lo = 1;
        if (g[2] <= g[lo]) lo = 2;
        m[0] = m[1] = m[2] = 1.f;
        m[lo] = 0.f;
    } else if (k == 1) {
        int w = 0;                         // winner = max; ties -> lowest index
        if (g[1] > g[w]) w = 1;
        if (g[2] > g[w]) w = 2;
        m[w] = 1.f;
    }
    float ssum = g[0] * m[0] + g[1] * m[1] + g[2] * m[2] + 1e-8f;
    gated[0] = g[0] * m[0] / ssum;
    gated[1] = g[1] * m[1] / ssum;
    gated[2] = g[2] * m[2] / ssum;
    mask[0] = m[0]; mask[1] = m[1]; mask[2] = m[2];
}

// ============================================================================
// Kernel 0: smem-tiled transpose w1 -> [n][k] + tf32 rounding   (launch idx 0)
// ============================================================================
__global__ void prep_transpose(const float* __restrict__ w1) {
    __shared__ float t[32][33];
    int bn = blockIdx.x & 31;            // n tile (HDIM/32 = 32)
    int bk = blockIdx.x >> 5;            // k tile (KDIM/32 = 96)
    int tx = threadIdx.x & 31;
    int ty = threadIdx.x >> 5;           // 0..7

    #pragma unroll
    for (int i = 0; i < 4; ++i)          // read w1[kk][n], coalesced over n
        t[ty + i * 8][tx] = w1[(size_t)(bk * 32 + ty + i * 8) * HDIM + bn * 32 + tx];
    __syncthreads();
    #pragma unroll
    for (int i = 0; i < 4; ++i)          // write g_w1t[n][kk], coalesced over kk
        g_w1t[(size_t)(bn * 32 + ty + i * 8) * KDIM + bk * 32 + tx] =
            to_tf32_rna(t[tx][ty + i * 8]);
}

// Kernel 0b: zero logits accumulator                             (launch idx 1)
__global__ void prep_zero() {
    int stride = gridDim.x * blockDim.x;
    for (int i = blockIdx.x * blockDim.x + threadIdx.x; i < BATCH * NEXP; i += stride)
        g_logits[i] = 0.f;
}

// Kernel 0c: reset refinement counter                            (launch idx 2)
__global__ void prep_init() {
    if (threadIdx.x == 0 && blockIdx.x == 0) g_rcount = 0;
}

// ============================================================================
// Kernel 1 (launch idx 3 -> ncu capture slot): tf32 mma.sync GEMM (h = x @ w1)
// fused with +b1, GELU, and h@w2 as per-row 3-float partial dots -> atomicAdd.
//   CTA tile 128x128, 4 warps (2x2) of 64x64, 128 threads, 2 CTAs/SM.
//   R14 structure (the measured winner): mbarrier producer/consumer ring,
//   full-wait at top of kt, fragment loads inline in the ks loop. Only delta
//   vs R14: empty-barrier arrivals are warp-elected (count 4) instead of 128
//   per-thread shared atomics per stage.
// ============================================================================
__global__ void __launch_bounds__(NTHREADS, 2)
gemm_kernel(const float* __restrict__ x, const float* __restrict__ b1,
            const float* __restrict__ w2) {
    extern __shared__ float smem[];
    float* As = smem;                        // [STAGES][BM][LDSF]
    float* Bs = smem + STAGES * A_STAGE;     // [STAGES][BN][LDSF]

    const int tid  = threadIdx.x;
    const int wid  = tid >> 5;
    const int lane = tid & 31;

    const int mt = blockIdx.x >> 3;
    const int nt = blockIdx.x & 7;
    const int m0 = mt * BM;
    const int n0 = nt * BN;

    const int wm = (wid >> 1) * 64;          // warp row offset (0/64)
    const int wn = (wid & 1) * 64;           // warp col offset (0/64)

    const uint32_t a_base = smem_u32(As);
    const uint32_t b_base = smem_u32(Bs);
    const uint32_t mb     = smem_u32(smem) + (uint32_t)SMEM_FLOATS * 4u;
    // full[s] = mb + s*8 ; empty[s] = mb + 24 + s*8

    if (tid == 0) {
        #pragma unroll
        for (int s = 0; s < STAGES; ++s) {
            MBARRIER_INIT(mb + s * 8, NTHREADS);      // full: 128 cp-arrivals
            MBARRIER_INIT(mb + 24 + s * 8, 4);        // empty: warp-elected
        }
    }
    __syncthreads();

    // ---- async copy of one stage (A: x fp32 raw; B: pre-rounded w1t) -------
    auto copy_stage = [&](int s, int k0) {
        const float* xg = x + (size_t)m0 * KDIM + k0;
        const float* bg = g_w1t + (size_t)n0 * KDIM + k0;
        uint32_t sa = a_base + (uint32_t)(s * A_STAGE) * 4u;
        uint32_t sb = b_base + (uint32_t)(s * B_STAGE) * 4u;
        #pragma unroll
        for (int i = 0; i < 8; ++i) {        // A: 1024 16B-chunks
            int f  = tid + i * NTHREADS;
            int m  = f >> 3;
            int kc = f & 7;
            CP_ASYNC_16(sa + (uint32_t)(m * LDSF + kc * 4) * 4u,
                        (const void*)(xg + (size_t)m * KDIM + kc * 4));
        }
        #pragma unroll
        for (int i = 0; i < 8; ++i) {        // B: 1024 16B-chunks
            int f  = tid + i * NTHREADS;
            int m  = f >> 3;
            int kc = f & 7;
            CP_ASYNC_16(sb + (uint32_t)(m * LDSF + kc * 4) * 4u,
                        (const void*)(bg + (size_t)m * KDIM + kc * 4));
        }
    };

    int pst = 0, pph = 1;        // producer cursor (phase 1: first empty-wait passes)
    int cst = 0, cph = 0;        // consumer cursor

    auto fill = [&](int k0) {
        MBARRIER_WAIT(mb + 24 + pst * 8, (uint32_t)pph);   // wait stage empty
        copy_stage(pst, k0);
        CP_MBAR_ARRIVE(mb + pst * 8);                      // arrive full on completion
        if (++pst == STAGES) { pst = 0; pph ^= 1; }
    };

    // ---- prologue: fill first STAGES-1 stages -------------------------------
    fill(0);
    fill(BK);

    float acc[4][8][4];
    #pragma unroll
    for (int a = 0; a < 4; ++a)
        #pragma unroll
        for (int b = 0; b < 8; ++b)
            #pragma unroll
            for (int c = 0; c < 4; ++c) acc[a][b][c] = 0.f;

    const int r  = lane >> 2;     // 0..7
    const int c4 = lane & 3;      // 0..3

    // ---- main loop ----------------------------------------------------------
    for (int kt = 0; kt < NKITER; ++kt) {
        int nk = kt + STAGES - 1;
        if (nk < NKITER) fill(nk * BK);

        MBARRIER_WAIT(mb + cst * 8, (uint32_t)cph);        // wait stage full

        const float* Asr = As + cst * A_STAGE + (wm + r) * LDSF;
        const float* Bsr = Bs + cst * B_STAGE + (wn + r) * LDSF;

        #pragma unroll
        for (int ks = 0; ks < 4; ++ks) {
            uint32_t af[4][4];
            uint32_t bf[8][2];
            #pragma unroll
            for (int fm = 0; fm < 4; ++fm) {
                const float* ap = Asr + fm * 16 * LDSF + ks * 8 + c4;
                af[fm][0] = __float_as_uint(ap[0]);
                af[fm][1] = __float_as_uint(ap[8 * LDSF]);
                af[fm][2] = __float_as_uint(ap[4]);
                af[fm][3] = __float_as_uint(ap[8 * LDSF + 4]);
            }
            #pragma unroll
            for (int fn = 0; fn < 8; ++fn) {
                const float* bp = Bsr + fn * 8 * LDSF + ks * 8 + c4;
                bf[fn][0] = __float_as_uint(bp[0]);
                bf[fn][1] = __float_as_uint(bp[4]);
            }
            #pragma unroll
            for (int fm = 0; fm < 4; ++fm)
                #pragma unroll
                for (int fn = 0; fn < 8; ++fn)
                    mma_tf32(acc[fm][fn], af[fm], bf[fn]);
        }

        __syncwarp();
        if (lane == 0) MBARRIER_ARRIVE(mb + 24 + cst * 8);   // warp-elected
        if (++cst == STAGES) { cst = 0; cph ^= 1; }
    }

    // ---- fused epilogue: +b1, GELU, dot with w2, reduce, atomicAdd ----------
    float bias[16], w2c[16][3];
    #pragma unroll
    for (int fn = 0; fn < 8; ++fn)
        #pragma unroll
        for (int j = 0; j < 2; ++j) {
            int q = fn * 2 + j;
            int n = n0 + wn + fn * 8 + c4 * 2 + j;
            bias[q]   = __ldg(&b1[n]);
            w2c[q][0] = __ldg(&w2[n * 3 + 0]);
            w2c[q][1] = __ldg(&w2[n * 3 + 1]);
            w2c[q][2] = __ldg(&w2[n * 3 + 2]);
        }

    #pragma unroll
    for (int fm = 0; fm < 4; ++fm) {
        #pragma unroll
        for (int h = 0; h < 2; ++h) {
            int m = m0 + wm + fm * 16 + r + h * 8;
            float p0 = 0.f, p1 = 0.f, p2 = 0.f;
            #pragma unroll
            for (int fn = 0; fn < 8; ++fn)
                #pragma unroll
                for (int j = 0; j < 2; ++j) {
                    int q = fn * 2 + j;
                    float g = gelu_exact(acc[fm][fn][h * 2 + j] + bias[q]);
                    p0 = fmaf(g, w2c[q][0], p0);
                    p1 = fmaf(g, w2c[q][1], p1);
                    p2 = fmaf(g, w2c[q][2], p2);
                }
            p0 += __shfl_xor_sync(0xffffffffu, p0, 1);
            p0 += __shfl_xor_sync(0xffffffffu, p0, 2);
            p1 += __shfl_xor_sync(0xffffffffu, p1, 1);
            p1 += __shfl_xor_sync(0xffffffffu, p1, 2);
            p2 += __shfl_xor_sync(0xffffffffu, p2, 1);
            p2 += __shfl_xor_sync(0xffffffffu, p2, 2);
            if (c4 == 0) {
                atomicAdd(&g_logits[m * 3 + 0], p0);
                atomicAdd(&g_logits[m * 3 + 1], p1);
                atomicAdd(&g_logits[m * 3 + 2], p2);
            }
        }
    }
}

// ============================================================================
// Kernel 2: softmax / top-k / mask / gated + near-tie flagging
// ============================================================================
__global__ void finalize_kernel(const float* __restrict__ b2, const int* __restrict__ kptr,
                                float* __restrict__ out) {
    int row = blockIdx.x * blockDim.x + threadIdx.x;
    if (row >= BATCH) return;
    int k = read_k(kptr);
    float l0 = g_logits[row * 3 + 0] + b2[0];
    float l1 = g_logits[row * 3 + 1] + b2[1];
    float l2 = g_logits[row * 3 + 2] + b2[2];
    float gated[3], mask[3];
    gate_from_logits(l0, l1, l2, k, gated, mask);
    out[(size_t)row * 3 + 0] = gated[0];
    out[(size_t)row * 3 + 1] = gated[1];
    out[(size_t)row * 3 + 2] = gated[2];
    out[(size_t)BATCH * 3 + row * 3 + 0] = mask[0];
    out[(size_t)BATCH * 3 + row * 3 + 1] = mask[1];
    out[(size_t)BATCH * 3 + row * 3 + 2] = mask[2];

    // flag rows whose top-k boundary gap is within ~8 sigma of tf32 error
    if (k == 1 || k == 2) {
        float a = l0, b = l1, cv = l2, t;
        if (a < b)  { t = a; a = b; b = t; }
        if (b < cv) { t = b; b = cv; cv = t; }
        if (a < b)  { t = a; a = b; b = t; }
        float gap = (k == 1) ? (a - b) : (b - cv);
        if (gap < 4e-3f) {
            int j = atomicAdd(&g_rcount, 1);
            if (j < RMAX) g_ridx[j] = row;
        }
    }
}

// zero the k-split staging used by refine1 (count rows only)
__global__ void refine0_kernel() {
    int count = g_rcount;
    if (count > RMAX) count = RMAX;
    size_t total = (size_t)count * HDIM;
    for (size_t i = blockIdx.x * blockDim.x + threadIdx.x; i < total;
         i += (size_t)gridDim.x * blockDim.x)
        g_hpart[i] = 0.f;
}

// ============================================================================
// Kernel 3: fp32-exact partial h for flagged rows.
//   item = (16 rows) x (64 h-cols) x (768-k quarter). 256 thr = 16 rows x
//   16 col-quads. No smem/barriers. Double-buffered float4 w1 batches.
// ============================================================================
#define RB_ROWS 16
#define RK      768
__global__ void __launch_bounds__(256)
refine1_kernel(const float* __restrict__ x, const float* __restrict__ w1) {
    int count = g_rcount;
    if (count > RMAX) count = RMAX;
    if (count == 0) return;
    int mchunks = (count + RB_ROWS - 1) / RB_ROWS;
    int nitems = mchunks * 16 * 4;               // x16 n-chunks, x4 k-quarters

    int tid  = threadIdx.x;
    int rloc = tid >> 4;          // 0..15 row within chunk
    int cg   = tid & 15;          // col-quad index

    for (int item = blockIdx.x; item < nitems; item += gridDim.x) {
        int kc = item & 3;
        int nc = (item >> 2) & 15;
        int mc = item >> 6;
        int n = nc * 64 + cg * 4;
        int j = mc * RB_ROWS + rloc;
        int jc = (j < count) ? j : (count - 1);
        const float* xr = x + (size_t)g_ridx[jc] * KDIM + kc * RK;
        const float* wp = w1 + (size_t)kc * RK * HDIM + n;

        float a0 = 0.f, a1 = 0.f, a2 = 0.f, a3 = 0.f;
        float4 wa0, wa1, wa2, wa3, wb0, wb1, wb2, wb3;
        wa0 = __ldg(reinterpret_cast<const float4*>(wp + 0 * HDIM));
        wa1 = __ldg(reinterpret_cast<const float4*>(wp + 1 * HDIM));
        wa2 = __ldg(reinterpret_cast<const float4*>(wp + 2 * HDIM));
        wa3 = __ldg(reinterpret_cast<const float4*>(wp + 3 * HDIM));
        for (int kk = 0; kk < RK; kk += 8) {
            wb0 = __ldg(reinterpret_cast<const float4*>(wp + (size_t)(kk + 4) * HDIM));
            wb1 = __ldg(reinterpret_cast<const float4*>(wp + (size_t)(kk + 5) * HDIM));
            wb2 = __ldg(reinterpret_cast<const float4*>(wp + (size_t)(kk + 6) * HDIM));
            wb3 = __ldg(reinterpret_cast<const float4*>(wp + (size_t)(kk + 7) * HDIM));
            float4 xv = __ldg(reinterpret_cast<const float4*>(xr + kk));
            a0 = fmaf(xv.x, wa0.x, a0); a1 = fmaf(xv.x, wa0.y, a1);
            a2 = fmaf(xv.x, wa0.z, a2); a3 = fmaf(xv.x, wa0.w, a3);
            a0 = fmaf(xv.y, wa1.x, a0); a1 = fmaf(xv.y, wa1.y, a1);
            a2 = fmaf(xv.y, wa1.z, a2); a3 = fmaf(xv.y, wa1.w, a3);
            a0 = fmaf(xv.z, wa2.x, a0); a1 = fmaf(xv.z, wa2.y, a1);
            a2 = fmaf(xv.z, wa2.z, a2); a3 = fmaf(xv.z, wa2.w, a3);
            a0 = fmaf(xv.w, wa3.x, a0); a1 = fmaf(xv.w, wa3.y, a1);
            a2 = fmaf(xv.w, wa3.z, a2); a3 = fmaf(xv.w, wa3.w, a3);
            if (kk + 8 < RK) {
                wa0 = __ldg(reinterpret_cast<const float4*>(wp + (size_t)(kk + 8)  * HDIM));
                wa1 = __ldg(reinterpret_cast<const float4*>(wp + (size_t)(kk + 9)  * HDIM));
                wa2 = __ldg(reinterpret_cast<const float4*>(wp + (size_t)(kk + 10) * HDIM));
                wa3 = __ldg(reinterpret_cast<const float4*>(wp + (size_t)(kk + 11) * HDIM));
            }
            float4 xw = __ldg(reinterpret_cast<const float4*>(xr + kk + 4));
            a0 = fmaf(xw.x, wb0.x, a0); a1 = fmaf(xw.x, wb0.y, a1);
            a2 = fmaf(xw.x, wb0.z, a2); a3 = fmaf(xw.x, wb0.w, a3);
            a0 = fmaf(xw.y, wb1.x, a0); a1 = fmaf(xw.y, wb1.y, a1);
            a2 = fmaf(xw.y, wb1.z, a2); a3 = fmaf(xw.y, wb1.w, a3);
            a0 = fmaf(xw.z, wb2.x, a0); a1 = fmaf(xw.z, wb2.y, a1);
            a2 = fmaf(xw.z, wb2.z, a2); a3 = fmaf(xw.z, wb2.w, a3);
            a0 = fmaf(xw.w, wb3.x, a0); a1 = fmaf(xw.w, wb3.y, a1);
            a2 = fmaf(xw.w, wb3.z, a2); a3 = fmaf(xw.w, wb3.w, a3);
        }

        if (j < count) {
            float* dst = g_hpart + ((size_t)j * HDIM + n);
            atomicAdd(&dst[0], a0);
            atomicAdd(&dst[1], a1);
            atomicAdd(&dst[2], a2);
            atomicAdd(&dst[3], a3);
        }
    }
}

// combine partial h -> GELU -> dot w2 -> refined logits
__global__ void refine1b_kernel(const float* __restrict__ b1, const float* __restrict__ w2) {
    int count = g_rcount;
    if (count > RMAX) count = RMAX;
    int warps = (gridDim.x * blockDim.x) >> 5;
    int gw = (blockIdx.x * blockDim.x + threadIdx.x) >> 5;
    int lane = threadIdx.x & 31;
    for (int j = gw; j < count; j += warps) {
        float p0 = 0.f, p1 = 0.f, p2 = 0.f;
        for (int nb = 0; nb < HDIM; nb += 32) {
            int n = nb + lane;
            float h = g_hpart[(size_t)j * HDIM + n] + __ldg(&b1[n]);
            float g = gelu_exact(h);
            p0 = fmaf(g, __ldg(&w2[n * 3 + 0]), p0);
            p1 = fmaf(g, __ldg(&w2[n * 3 + 1]), p1);
            p2 = fmaf(g, __ldg(&w2[n * 3 + 2]), p2);
        }
        #pragma unroll
        for (int off = 16; off > 0; off >>= 1) {
            p0 += __shfl_xor_sync(0xffffffffu, p0, off);
            p1 += __shfl_xor_sync(0xffffffffu, p1, off);
            p2 += __shfl_xor_sync(0xffffffffu, p2, off);
        }
        if (lane == 0) {
            g_rlogits[j * 3 + 0] = p0;
            g_rlogits[j * 3 + 1] = p1;
            g_rlogits[j * 3 + 2] = p2;
        }
    }
}

// ============================================================================
// Kernel 4: rewrite outputs for flagged rows from refined (exact) logits
// ============================================================================
__global__ void refine2_kernel(const float* __restrict__ b2, const int* __restrict__ kptr,
                               float* __restrict__ out) {
    int k = read_k(kptr);
    int count = g_rcount;
    if (count > RMAX) count = RMAX;
    for (int j = blockIdx.x * blockDim.x + threadIdx.x; j < count; j += gridDim.x * blockDim.x) {
        int row = g_ridx[j];
        float l0 = g_rlogits[j * 3 + 0] + b2[0];
        float l1 = g_rlogits[j * 3 + 1] + b2[1];
        float l2 = g_rlogits[j * 3 + 2] + b2[2];
        float gated[3], mask[3];
        gate_from_logits(l0, l1, l2, k, gated, mask);
        out[(size_t)row * 3 + 0] = gated[0];
        out[(size_t)row * 3 + 1] = gated[1];
        out[(size_t)row * 3 + 2] = gated[2];
        out[(size_t)BATCH * 3 + row * 3 + 0] = mask[0];
        out[(size_t)BATCH * 3 + row * 3 + 1] = mask[1];
        out[(size_t)BATCH * 3 + row * 3 + 2] = mask[2];
    }
}

// ============================================================================
// Launch — gemm deliberately placed at launch index 3 (ncu capture slot)
// ============================================================================
extern "C" void kernel_launch(void* const* d_in, const int* in_sizes, int n_in,
                              void* d_out, int out_size) {
    const float* x  = (const float*)d_in[0];
    const float* w1 = (const float*)d_in[1];
    const float* b1 = (const float*)d_in[2];
    const float* w2 = (const float*)d_in[3];
    const float* b2 = (const float*)d_in[4];
    const int*   kp = (const int*)d_in[5];
    float* out = (float*)d_out;
    (void)in_sizes; (void)n_in; (void)out_size;

    static bool attr_set = false;
    if (!attr_set) {
        cudaFuncSetAttribute(gemm_kernel, cudaFuncAttributeMaxDynamicSharedMemorySize, SMEM_BYTES);
        attr_set = true;
    }

    prep_transpose<<<(HDIM / 32) * (KDIM / 32), 256>>>(w1);          // idx 0
    prep_zero<<<256, 256>>>();                                       // idx 1
    prep_init<<<1, 32>>>();                                          // idx 2
    gemm_kernel<<<(BATCH / BM) * (HDIM / BN), NTHREADS, SMEM_BYTES>>>(x, b1, w2);  // idx 3
    finalize_kernel<<<BATCH / 256, 256>>>(b2, kp, out);              // idx 4
    refine0_kernel<<<256, 256>>>();                                  // idx 5
    refine1_kernel<<<1024, 256>>>(x, w1);                            // idx 6
    refine1b_kernel<<<128, 256>>>(b1, w2);                           // idx 7
    refine2_kernel<<<64, 256>>>(b2, kp, out);                        // idx 8
}